// round 8
// baseline (speedup 1.0000x reference)
#include <cuda_runtime.h>
#include <cstdint>

#define S_ 512
#define L_ 256
#define H_ 768
#define P_ 8
#define K_ 8
#define H4_ 192                  // float4 per full row
#define HH4_ 96                  // float4 per half row
#define THREADS_ 96
#define CHUNK_ 32                // rows per pipeline stage
#define NSTG_ 2
#define MAXE_ 192                // worst-case entries (3*8*8)

// dynamic smem layout (bytes)
#define STAGEB_   (CHUNK_ * HH4_ * 16)          // 49152 per stage
#define OFF_EIDX  (NSTG_ * STAGEB_)             // 98304
#define OFF_EW    (OFF_EIDX + MAXE_ * 4)
#define OFF_EROLE (OFF_EW   + MAXE_ * 4)
#define SMEM_TOTAL (OFF_EROLE + MAXE_ * 4)      // 100608

extern __shared__ __align__(16) unsigned char dsm[];

__device__ __forceinline__ uint32_t smem_u32(const void* p) {
    uint32_t a;
    asm("{ .reg .u64 t; cvta.to.shared.u64 t, %1; cvt.u32.u64 %0, t; }" : "=r"(a) : "l"(p));
    return a;
}

__device__ __forceinline__ void cp16(uint32_t dst, const void* src) {
    asm volatile("cp.async.cg.shared.global [%0], [%1], 16;" :: "r"(dst), "l"(src) : "memory");
}
__device__ __forceinline__ void cp_commit() {
    asm volatile("cp.async.commit_group;" ::: "memory");
}
template <int N>
__device__ __forceinline__ void cp_wait() {
    asm volatile("cp.async.wait_group %0;" :: "n"(N) : "memory");
}

__global__ __launch_bounds__(THREADS_, 2)
void srl_pool_kernel(const float* __restrict__ emb,
                     const int* __restrict__ idxV,  const int* __restrict__ mV,
                     const int* __restrict__ idxA0, const int* __restrict__ mA0,
                     const int* __restrict__ idxA1, const int* __restrict__ mA1,
                     const int* __restrict__ pred,
                     float* __restrict__ out)
{
    const int s     = blockIdx.x;
    const int hhalf = blockIdx.y;
    const int tid   = threadIdx.x;

    int*   e_idx  = reinterpret_cast<int*>(dsm + OFF_EIDX);
    float* e_w    = reinterpret_cast<float*>(dsm + OFF_EW);
    int*   e_role = reinterpret_cast<int*>(dsm + OFF_EROLE);

    __shared__ int s_nct;

    // ---------- Phase 1: 24-lane warp-scan compaction (role-major) ----------
    if (tid < 3 * P_) {
        const unsigned FULL = 0x00FFFFFFu;
        const int role = tid >> 3;
        const int p    = tid & 7;
        const int* __restrict__ idx =
            (role == 0) ? idxV : (role == 1) ? idxA0 : idxA1;
        const int* __restrict__ msk =
            (role == 0) ? mV : (role == 1) ? mA0 : mA1;

        const int base = (s * P_ + p) * K_;
        int4 iv0 = *reinterpret_cast<const int4*>(idx + base);
        int4 iv1 = *reinterpret_cast<const int4*>(idx + base + 4);
        int4 mv0 = *reinterpret_cast<const int4*>(msk + base);
        int4 mv1 = *reinterpret_cast<const int4*>(msk + base + 4);
        int4 pv0 = *reinterpret_cast<const int4*>(pred + s * P_);
        int4 pv1 = *reinterpret_cast<const int4*>(pred + s * P_ + 4);

        int li[K_] = { iv0.x, iv0.y, iv0.z, iv0.w, iv1.x, iv1.y, iv1.z, iv1.w };
        int lm[K_] = { mv0.x, mv0.y, mv0.z, mv0.w, mv1.x, mv1.y, mv1.z, mv1.w };

        int lv[K_];
        int cnt = 0;
        #pragma unroll
        for (int k = 0; k < K_; k++) {
            int v = (lm[k] != 0) & (li[k] < L_) & (li[k] >= 0);
            li[k] = min(max(li[k], 0), L_ - 1);
            lv[k] = v;
            cnt  += v;
        }

        int pown  = (p < 4) ? ((const int*)&pv0)[p] : ((const int*)&pv1)[p - 4];
        int npred = (pv0.x != 0) + (pv0.y != 0) + (pv0.z != 0) + (pv0.w != 0)
                  + (pv1.x != 0) + (pv1.y != 0) + (pv1.z != 0) + (pv1.w != 0);

        int take = (pown != 0 && cnt > 0 && npred > 0);
        float w  = take ? 1.0f / ((float)cnt * (float)npred) : 0.0f;
        int eff  = take ? cnt : 0;

        int off = eff;   // inclusive scan across 24 lanes
        #pragma unroll
        for (int d = 1; d < 32; d <<= 1) {
            int y = __shfl_up_sync(FULL, off, d);
            if (tid >= d) off += y;
        }
        int pos = off - eff;

        if (take) {
            #pragma unroll
            for (int k = 0; k < K_; k++) {
                if (lv[k]) {
                    e_idx[pos]  = li[k];
                    e_w[pos]    = w;
                    e_role[pos] = role;
                    pos++;
                }
            }
        }
        if (tid == 23) s_nct = off;
    }
    __syncthreads();

    // ---------- Phase 2: cp.async deep-pipelined gather ----------
    const int nct = s_nct;
    const int nch = (nct + CHUNK_ - 1) / CHUNK_;

    // this thread's global column: hhalf half + tid-th float4
    const float* __restrict__ gcol =
        emb + (size_t)s * L_ * H_ + (size_t)(hhalf * HH4_ + tid) * 4;
    const uint32_t stage_base = smem_u32(dsm) + (uint32_t)tid * 16;

    // issue chunk c (each thread copies its own 16B slice of each row)
    #define ISSUE(C) do {                                                      \
        int beg  = (C) * CHUNK_;                                               \
        int bcnt = min(CHUNK_, nct - beg);                                     \
        uint32_t dst = stage_base + ((C) & 1) * STAGEB_;                       \
        for (int k = 0; k < bcnt; k++) {                                       \
            cp16(dst + (uint32_t)k * (HH4_ * 16),                              \
                 gcol + (size_t)e_idx[beg + k] * H_);                          \
        }                                                                      \
        cp_commit();                                                           \
    } while (0)

    float4 a0 = make_float4(0.f, 0.f, 0.f, 0.f);
    float4 a1 = a0, a2 = a0;

    if (nch > 0) ISSUE(0);
    if (nch > 1) ISSUE(1);
    int issued = min(nch, 2);

    const float4* __restrict__ stg =
        reinterpret_cast<const float4*>(dsm) + tid;

    for (int c = 0; c < nch; c++) {
        // groups pending beyond chunk c: issued - c - 1 (0 or 1)
        if (issued - c - 1 >= 1) cp_wait<1>(); else cp_wait<0>();

        const int beg  = c * CHUNK_;
        const int bcnt = min(CHUNK_, nct - beg);
        const float4* __restrict__ vb = stg + (c & 1) * (CHUNK_ * HH4_);

        for (int k = 0; k < bcnt; k++) {
            float  w = e_w[beg + k];
            int    r = e_role[beg + k];
            float4 v = vb[k * HH4_];
            if (r == 0) {
                a0.x += w*v.x; a0.y += w*v.y; a0.z += w*v.z; a0.w += w*v.w;
            } else if (r == 1) {
                a1.x += w*v.x; a1.y += w*v.y; a1.z += w*v.z; a1.w += w*v.w;
            } else {
                a2.x += w*v.x; a2.y += w*v.y; a2.z += w*v.z; a2.w += w*v.w;
            }
        }
        if (issued < nch) { ISSUE(issued); issued++; }
    }
    #undef ISSUE

    // Output: (e_V, e_A0, e_A1) role-major, each (S, H) f32.
    float4* __restrict__ out4 =
        reinterpret_cast<float4*>(out) + (size_t)s * H4_ + hhalf * HH4_ + tid;
    out4[(size_t)0 * S_ * H4_] = a0;
    out4[(size_t)1 * S_ * H4_] = a1;
    out4[(size_t)2 * S_ * H4_] = a2;
}

extern "C" void kernel_launch(void* const* d_in, const int* in_sizes, int n_in,
                              void* d_out, int out_size)
{
    const float* emb   = (const float*)d_in[0];
    const int*   idxV  = (const int*)d_in[1];
    const int*   mV    = (const int*)d_in[2];
    const int*   idxA0 = (const int*)d_in[3];
    const int*   mA0   = (const int*)d_in[4];
    const int*   idxA1 = (const int*)d_in[5];
    const int*   mA1   = (const int*)d_in[6];
    const int*   pred  = (const int*)d_in[7];
    float* out = (float*)d_out;

    static int attr_set = 0;
    if (!attr_set) {
        cudaFuncSetAttribute(srl_pool_kernel,
                             cudaFuncAttributeMaxDynamicSharedMemorySize, SMEM_TOTAL);
        attr_set = 1;
    }
    dim3 grid(S_, 2);
    srl_pool_kernel<<<grid, THREADS_, SMEM_TOTAL>>>(emb, idxV, mV, idxA0, mA0,
                                                    idxA1, mA1, pred, out);
}

// round 9
// speedup vs baseline: 1.4981x; 1.4981x over previous
#include <cuda_runtime.h>

#define S_ 512
#define L_ 256
#define H_ 768
#define P_ 8
#define K_ 8
#define H4_ 192
#define THREADS_ 192
#define MAXR_ 196            // max distinct rows (192) + pad slack

__global__ __launch_bounds__(THREADS_, 1)
void srl_pool_kernel(const float* __restrict__ emb,
                     const int* __restrict__ idxV,  const int* __restrict__ mV,
                     const int* __restrict__ idxA0, const int* __restrict__ mA0,
                     const int* __restrict__ idxA1, const int* __restrict__ mA1,
                     const int* __restrict__ pred,
                     float* __restrict__ out)
{
    const int s   = blockIdx.x;
    const int tid = threadIdx.x;

    __shared__ float    wtab[3][L_];     // per-role per-row accumulated weight
    __shared__ unsigned bmap[8];         // 256-bit "row used" bitmap
    __shared__ int      rows[MAXR_];
    __shared__ float    lw0[MAXR_], lw1[MAXR_], lw2[MAXR_];
    __shared__ int      s_nr;

    // Zero tables: 3*256 floats + bitmap
    #pragma unroll
    for (int j = tid; j < 3 * L_; j += THREADS_)
        (&wtab[0][0])[j] = 0.0f;
    if (tid < 8) bmap[tid] = 0u;
    __syncthreads();

    // ---------- Phase 1: 24 lanes, one per (role, p); scatter weights ----------
    if (tid < 3 * P_) {
        const int role = tid >> 3;
        const int p    = tid & 7;
        const int* __restrict__ idx =
            (role == 0) ? idxV : (role == 1) ? idxA0 : idxA1;
        const int* __restrict__ msk =
            (role == 0) ? mV : (role == 1) ? mA0 : mA1;

        const int base = (s * P_ + p) * K_;
        int4 iv0 = *reinterpret_cast<const int4*>(idx + base);
        int4 iv1 = *reinterpret_cast<const int4*>(idx + base + 4);
        int4 mv0 = *reinterpret_cast<const int4*>(msk + base);
        int4 mv1 = *reinterpret_cast<const int4*>(msk + base + 4);
        int4 pv0 = *reinterpret_cast<const int4*>(pred + s * P_);
        int4 pv1 = *reinterpret_cast<const int4*>(pred + s * P_ + 4);

        int li[K_] = { iv0.x, iv0.y, iv0.z, iv0.w, iv1.x, iv1.y, iv1.z, iv1.w };
        int lm[K_] = { mv0.x, mv0.y, mv0.z, mv0.w, mv1.x, mv1.y, mv1.z, mv1.w };

        int lv[K_];
        int cnt = 0;
        #pragma unroll
        for (int k = 0; k < K_; k++) {
            int v = (lm[k] != 0) & (li[k] < L_) & (li[k] >= 0);
            li[k] = min(max(li[k], 0), L_ - 1);
            lv[k] = v;
            cnt  += v;
        }

        int pown  = (p < 4) ? ((const int*)&pv0)[p] : ((const int*)&pv1)[p - 4];
        int npred = (pv0.x != 0) + (pv0.y != 0) + (pv0.z != 0) + (pv0.w != 0)
                  + (pv1.x != 0) + (pv1.y != 0) + (pv1.z != 0) + (pv1.w != 0);

        if (pown != 0 && cnt > 0 && npred > 0) {
            float w = 1.0f / ((float)cnt * (float)npred);
            #pragma unroll
            for (int k = 0; k < K_; k++) {
                if (lv[k]) {
                    atomicAdd(&wtab[role][li[k]], w);
                    atomicOr(&bmap[li[k] >> 5], 1u << (li[k] & 31));
                }
            }
        }
    }
    __syncthreads();

    // ---------- Compaction: warp 0, deterministic bit-scan over 8 words ----------
    if (tid < 32) {
        int running = 0;
        #pragma unroll
        for (int wd = 0; wd < 8; wd++) {
            unsigned bits = bmap[wd];
            int set = (bits >> tid) & 1;
            int pos = running + __popc(bits & ((1u << tid) - 1u));
            if (set) {
                int row = wd * 32 + tid;
                rows[pos] = row;
                lw0[pos]  = wtab[0][row];
                lw1[pos]  = wtab[1][row];
                lw2[pos]  = wtab[2][row];
            }
            running += __popc(bits);
        }
        if (tid == 0) s_nr = running;
        // pad to multiple of 4 (row 0, weights 0 — harmless L1-hit loads)
        int nrp = (running + 3) & ~3;
        if (tid < nrp - running) {
            rows[running + tid] = 0;
            lw0[running + tid]  = 0.0f;
            lw1[running + tid]  = 0.0f;
            lw2[running + tid]  = 0.0f;
        }
    }
    __syncthreads();

    // ---------- Phase 2: gather each distinct row once; FMA into 3 accums ----------
    const float4* __restrict__ emb4 =
        reinterpret_cast<const float4*>(emb) + (size_t)s * L_ * H4_ + tid;

    float4 a0 = make_float4(0.f, 0.f, 0.f, 0.f);
    float4 a1 = a0, a2 = a0;

    const int nrp = (s_nr + 3) & ~3;

    for (int j = 0; j < nrp; j += 4) {
        int i0 = rows[j+0], i1 = rows[j+1], i2 = rows[j+2], i3 = rows[j+3];
        float4 v0 = emb4[i0 * H4_];
        float4 v1 = emb4[i1 * H4_];
        float4 v2 = emb4[i2 * H4_];
        float4 v3 = emb4[i3 * H4_];

        float u0 = lw0[j+0], u1 = lw0[j+1], u2 = lw0[j+2], u3 = lw0[j+3];
        float x0 = lw1[j+0], x1 = lw1[j+1], x2 = lw1[j+2], x3 = lw1[j+3];
        float y0 = lw2[j+0], y1 = lw2[j+1], y2 = lw2[j+2], y3 = lw2[j+3];

        a0.x += u0*v0.x; a0.y += u0*v0.y; a0.z += u0*v0.z; a0.w += u0*v0.w;
        a1.x += x0*v0.x; a1.y += x0*v0.y; a1.z += x0*v0.z; a1.w += x0*v0.w;
        a2.x += y0*v0.x; a2.y += y0*v0.y; a2.z += y0*v0.z; a2.w += y0*v0.w;

        a0.x += u1*v1.x; a0.y += u1*v1.y; a0.z += u1*v1.z; a0.w += u1*v1.w;
        a1.x += x1*v1.x; a1.y += x1*v1.y; a1.z += x1*v1.z; a1.w += x1*v1.w;
        a2.x += y1*v1.x; a2.y += y1*v1.y; a2.z += y1*v1.z; a2.w += y1*v1.w;

        a0.x += u2*v2.x; a0.y += u2*v2.y; a0.z += u2*v2.z; a0.w += u2*v2.w;
        a1.x += x2*v2.x; a1.y += x2*v2.y; a1.z += x2*v2.z; a1.w += x2*v2.w;
        a2.x += y2*v2.x; a2.y += y2*v2.y; a2.z += y2*v2.z; a2.w += y2*v2.w;

        a0.x += u3*v3.x; a0.y += u3*v3.y; a0.z += u3*v3.z; a0.w += u3*v3.w;
        a1.x += x3*v3.x; a1.y += x3*v3.y; a1.z += x3*v3.z; a1.w += x3*v3.w;
        a2.x += y3*v3.x; a2.y += y3*v3.y; a2.z += y3*v3.z; a2.w += y3*v3.w;
    }

    // Output: (e_V, e_A0, e_A1) role-major, each (S, H) f32.
    float4* __restrict__ out4 = reinterpret_cast<float4*>(out);
    out4[((size_t)0 * S_ + s) * H4_ + tid] = a0;
    out4[((size_t)1 * S_ + s) * H4_ + tid] = a1;
    out4[((size_t)2 * S_ + s) * H4_ + tid] = a2;
}

extern "C" void kernel_launch(void* const* d_in, const int* in_sizes, int n_in,
                              void* d_out, int out_size)
{
    const float* emb   = (const float*)d_in[0];
    const int*   idxV  = (const int*)d_in[1];
    const int*   mV    = (const int*)d_in[2];
    const int*   idxA0 = (const int*)d_in[3];
    const int*   mA0   = (const int*)d_in[4];
    const int*   idxA1 = (const int*)d_in[5];
    const int*   mA1   = (const int*)d_in[6];
    const int*   pred  = (const int*)d_in[7];
    float* out = (float*)d_out;

    srl_pool_kernel<<<S_, THREADS_>>>(emb, idxV, mV, idxA0, mA0, idxA1, mA1, pred, out);
}

// round 10
// speedup vs baseline: 1.7047x; 1.1379x over previous
#include <cuda_runtime.h>

#define S_ 512
#define L_ 256
#define H_ 768
#define P_ 8
#define K_ 8
#define H4_ 192             // float4 per full row
#define HH4_ 96             // float4 per half row
#define SEG_ 72             // per-role capacity (64 max + 8 round-up slack)
#define THREADS_ 96

__global__ __launch_bounds__(THREADS_)
void srl_pool_kernel(const float* __restrict__ emb,
                     const int* __restrict__ idxV,  const int* __restrict__ mV,
                     const int* __restrict__ idxA0, const int* __restrict__ mA0,
                     const int* __restrict__ idxA1, const int* __restrict__ mA1,
                     const int* __restrict__ pred,
                     float* __restrict__ out)
{
    const int s     = blockIdx.x;
    const int hhalf = blockIdx.y;          // which 384-float half of H
    const int tid   = threadIdx.x;         // 0..95

    __shared__ int   s_idx[3][SEG_];
    __shared__ float s_w[3][SEG_];
    __shared__ int   s_n[3];

    // Pre-zero lists (padded slots: idx=0, w=0 -> harmless L1-hit loads).
    #pragma unroll
    for (int j = tid; j < 3 * SEG_; j += THREADS_) {
        s_idx[j / SEG_][j % SEG_] = 0;
        s_w[j / SEG_][j % SEG_]   = 0.0f;
    }
    if (tid < 3) s_n[tid] = 0;
    __syncthreads();

    // ---------- Phase 1: 24 lanes, one per (role, p); vectorized loads ----------
    if (tid < 3 * P_) {
        const int role = tid >> 3;
        const int p    = tid & 7;
        const int* __restrict__ idx =
            (role == 0) ? idxV : (role == 1) ? idxA0 : idxA1;
        const int* __restrict__ msk =
            (role == 0) ? mV : (role == 1) ? mA0 : mA1;

        const int base = (s * P_ + p) * K_;
        int4 iv0 = *reinterpret_cast<const int4*>(idx + base);
        int4 iv1 = *reinterpret_cast<const int4*>(idx + base + 4);
        int4 mv0 = *reinterpret_cast<const int4*>(msk + base);
        int4 mv1 = *reinterpret_cast<const int4*>(msk + base + 4);
        int4 pv0 = *reinterpret_cast<const int4*>(pred + s * P_);
        int4 pv1 = *reinterpret_cast<const int4*>(pred + s * P_ + 4);

        int li[K_] = { iv0.x, iv0.y, iv0.z, iv0.w, iv1.x, iv1.y, iv1.z, iv1.w };
        int lm[K_] = { mv0.x, mv0.y, mv0.z, mv0.w, mv1.x, mv1.y, mv1.z, mv1.w };

        int lv[K_];
        int cnt = 0;
        #pragma unroll
        for (int k = 0; k < K_; k++) {
            int v = (lm[k] != 0) & (li[k] < L_) & (li[k] >= 0);
            li[k] = min(max(li[k], 0), L_ - 1);
            lv[k] = v;
            cnt  += v;
        }

        int pown  = (p < 4) ? ((const int*)&pv0)[p] : ((const int*)&pv1)[p - 4];
        int npred = (pv0.x != 0) + (pv0.y != 0) + (pv0.z != 0) + (pv0.w != 0)
                  + (pv1.x != 0) + (pv1.y != 0) + (pv1.z != 0) + (pv1.w != 0);

        float w = 0.0f;
        if (pown != 0 && cnt > 0 && npred > 0)
            w = 1.0f / ((float)cnt * (float)npred);

        if (w != 0.0f) {
            int pos = atomicAdd(&s_n[role], cnt);
            #pragma unroll
            for (int k = 0; k < K_; k++) {
                if (lv[k]) {
                    s_idx[role][pos] = li[k];
                    s_w[role][pos]   = w;
                    pos++;
                }
            }
        }
    }
    __syncthreads();

    // ---------- Phase 2: true MLP=8 weighted row-sum over this H-half ----------
    const float4* __restrict__ embc =
        reinterpret_cast<const float4*>(emb) + (size_t)s * L_ * H4_ + hhalf * HH4_ + tid;

    float4 a0 = make_float4(0.f, 0.f, 0.f, 0.f);
    float4 a1 = a0, a2 = a0;

    // Round counts up to multiple of 8 so every batch is full (pads are w=0,row=0).
    const int n0 = (s_n[0] + 7) & ~7;
    const int n1 = (s_n[1] + 7) & ~7;
    const int n2 = (s_n[2] + 7) & ~7;

    #define AXPY8(ACC, R, NR)                                                   \
    for (int j = 0; j < (NR); j += 8) {                                         \
        int i0 = s_idx[R][j+0], i1 = s_idx[R][j+1];                             \
        int i2 = s_idx[R][j+2], i3 = s_idx[R][j+3];                             \
        int i4 = s_idx[R][j+4], i5 = s_idx[R][j+5];                             \
        int i6 = s_idx[R][j+6], i7 = s_idx[R][j+7];                             \
        float4 v0 = embc[i0 * H4_];                                             \
        float4 v1 = embc[i1 * H4_];                                             \
        float4 v2 = embc[i2 * H4_];                                             \
        float4 v3 = embc[i3 * H4_];                                             \
        float4 v4 = embc[i4 * H4_];                                             \
        float4 v5 = embc[i5 * H4_];                                             \
        float4 v6 = embc[i6 * H4_];                                             \
        float4 v7 = embc[i7 * H4_];                                             \
        float w0 = s_w[R][j+0], w1 = s_w[R][j+1];                               \
        float w2 = s_w[R][j+2], w3 = s_w[R][j+3];                               \
        float w4 = s_w[R][j+4], w5 = s_w[R][j+5];                               \
        float w6 = s_w[R][j+6], w7 = s_w[R][j+7];                               \
        ACC.x += w0*v0.x; ACC.y += w0*v0.y; ACC.z += w0*v0.z; ACC.w += w0*v0.w; \
        ACC.x += w1*v1.x; ACC.y += w1*v1.y; ACC.z += w1*v1.z; ACC.w += w1*v1.w; \
        ACC.x += w2*v2.x; ACC.y += w2*v2.y; ACC.z += w2*v2.z; ACC.w += w2*v2.w; \
        ACC.x += w3*v3.x; ACC.y += w3*v3.y; ACC.z += w3*v3.z; ACC.w += w3*v3.w; \
        ACC.x += w4*v4.x; ACC.y += w4*v4.y; ACC.z += w4*v4.z; ACC.w += w4*v4.w; \
        ACC.x += w5*v5.x; ACC.y += w5*v5.y; ACC.z += w5*v5.z; ACC.w += w5*v5.w; \
        ACC.x += w6*v6.x; ACC.y += w6*v6.y; ACC.z += w6*v6.z; ACC.w += w6*v6.w; \
        ACC.x += w7*v7.x; ACC.y += w7*v7.y; ACC.z += w7*v7.z; ACC.w += w7*v7.w; \
    }

    AXPY8(a0, 0, n0)
    AXPY8(a1, 1, n1)
    AXPY8(a2, 2, n2)
    #undef AXPY8

    // Output: (e_V, e_A0, e_A1) role-major, each (S, H) f32.
    float4* __restrict__ out4 =
        reinterpret_cast<float4*>(out) + (size_t)s * H4_ + hhalf * HH4_ + tid;
    out4[(size_t)0 * S_ * H4_] = a0;
    out4[(size_t)1 * S_ * H4_] = a1;
    out4[(size_t)2 * S_ * H4_] = a2;
}

extern "C" void kernel_launch(void* const* d_in, const int* in_sizes, int n_in,
                              void* d_out, int out_size)
{
    const float* emb   = (const float*)d_in[0];
    const int*   idxV  = (const int*)d_in[1];
    const int*   mV    = (const int*)d_in[2];
    const int*   idxA0 = (const int*)d_in[3];
    const int*   mA0   = (const int*)d_in[4];
    const int*   idxA1 = (const int*)d_in[5];
    const int*   mA1   = (const int*)d_in[6];
    const int*   pred  = (const int*)d_in[7];
    float* out = (float*)d_out;

    dim3 grid(S_, 2);
    srl_pool_kernel<<<grid, THREADS_>>>(emb, idxV, mV, idxA0, mA0, idxA1, mA1, pred, out);
}